// round 2
// baseline (speedup 1.0000x reference)
#include <cuda_runtime.h>
#include <cuda_bf16.h>

// s_t[c] = h_t . fcW[c,:]  for t in [0,128), c in {0,1}
__device__ float2 g_s[128];

__device__ __forceinline__ float sigmoidf_(float x) { return 1.0f / (1.0f + expf(-x)); }

// Stage 1: one block, 256 threads (one per hidden unit h).
// Computes the (input-independent) LSTM gate constants from the analytically
// collapsed quantum circuit, runs the c-recursion over T=128 steps, and
// reduces h_t against fcW into g_s[t] = (s_t[0], s_t[1]).
__global__ void qlstm_stage1(const float* __restrict__ qw,   // (4,2,8)
                             const float* __restrict__ Wo,   // (4,256,8)
                             const float* __restrict__ bo,   // (4,256)
                             const float* __restrict__ fcW)  // (2,256)
{
    __shared__ float zeta[4][8];
    __shared__ float zz[4][8];
    __shared__ float hbuf[32][264];   // [t_local][h], padded row stride (bank-safe)

    const int tid = threadIdx.x;

    // Per-wire <Z> factor: zeta[g][j] = -sin(qw[g,0,j])  (RX/RZ provably drop out)
    if (tid < 32) {
        int g = tid >> 3, j = tid & 7;
        zeta[g][j] = -sinf(qw[g * 16 + j]);
    }
    __syncthreads();

    // CNOT-ring Heisenberg products:
    //   z[g][0] = prod_{j=1..7} zeta_j ;  z[g][w] = prod_{j=0..w} zeta_j (w>=1)
    if (tid < 32) {
        int g = tid >> 3, w = tid & 7;
        float p = 1.0f;
        if (w == 0) { for (int j = 1; j < 8; j++)  p *= zeta[g][j]; }
        else        { for (int j = 0; j <= w; j++) p *= zeta[g][j]; }
        zz[g][w] = p;
    }
    __syncthreads();

    // Constant gate pre-activations for this hidden unit
    const int h = tid;
    float pre[4];
#pragma unroll
    for (int g = 0; g < 4; g++) {
        float s = bo[g * 256 + h];
        const float* wrow = Wo + (g * 256 + h) * 8;
#pragma unroll
        for (int q = 0; q < 8; q++) s += wrow[q] * zz[g][q];
        pre[g] = s;
    }
    const float f  = sigmoidf_(pre[0]);
    const float ig = sigmoidf_(pre[1]) * tanhf(pre[2]);
    const float oo = sigmoidf_(pre[3]);
    const float w0 = fcW[h];
    const float w1 = fcW[256 + h];

    float c = 0.0f;
    for (int chunk = 0; chunk < 4; chunk++) {
        // Phase 1: 32 recursion steps, stash h_t per (t_local, h)
#pragma unroll
        for (int tl = 0; tl < 32; tl++) {
            c = f * c + ig;
            hbuf[tl][h] = oo * tanhf(c);
        }
        __syncthreads();
        // Phase 2: 8 threads per t reduce 256 h against fcW rows
        {
            int tl = tid >> 3, r = tid & 7;
            float s0 = 0.0f, s1 = 0.0f;
#pragma unroll
            for (int k = 0; k < 32; k++) {
                int hh = r + (k << 3);
                float hv = hbuf[tl][hh];
                s0 += hv * fcW[hh];
                s1 += hv * fcW[256 + hh];
            }
#pragma unroll
            for (int off = 4; off; off >>= 1) {
                s0 += __shfl_xor_sync(0xffffffffu, s0, off);
                s1 += __shfl_xor_sync(0xffffffffu, s1, off);
            }
            if (r == 0) g_s[chunk * 32 + tl] = make_float2(s0, s1);
        }
        __syncthreads();
    }
    (void)w0; (void)w1; // (fcW read directly in phase 2)
}

// Stage 2: one warp per batch row. Reads the only input that matters: x (mask).
__global__ void qlstm_stage2(const int* __restrict__ x,     // (1024,128)
                             const float* __restrict__ fcb, // (2,)
                             float* __restrict__ out)       // (1024,2)
{
    const int gw   = (blockIdx.x * blockDim.x + threadIdx.x) >> 5;
    const int lane = threadIdx.x & 31;
    if (gw >= 1024) return;

    const int* xr = x + gw * 128;
    float a0 = 0.0f, a1 = 0.0f, cnt = 0.0f;
#pragma unroll
    for (int k = 0; k < 4; k++) {
        int t = lane + (k << 5);
        if (xr[t] != 0) {
            float2 s = g_s[t];
            a0 += s.x; a1 += s.y; cnt += 1.0f;
        }
    }
#pragma unroll
    for (int off = 16; off; off >>= 1) {
        a0  += __shfl_xor_sync(0xffffffffu, a0, off);
        a1  += __shfl_xor_sync(0xffffffffu, a1, off);
        cnt += __shfl_xor_sync(0xffffffffu, cnt, off);
    }
    if (lane == 0) {
        float inv = 1.0f / (cnt + 1e-9f);
        out[gw * 2 + 0] = a0 * inv + fcb[0];
        out[gw * 2 + 1] = a1 * inv + fcb[1];
    }
}

extern "C" void kernel_launch(void* const* d_in, const int* in_sizes, int n_in,
                              void* d_out, int out_size)
{
    // metadata order: x, embed, Wi, bi, qw, Wo, bo, fcW, fcb
    const int*   x   = (const int*)  d_in[0];
    const float* qw  = (const float*)d_in[4];
    const float* Wo  = (const float*)d_in[5];
    const float* bo  = (const float*)d_in[6];
    const float* fcW = (const float*)d_in[7];
    const float* fcb = (const float*)d_in[8];
    float* out = (float*)d_out;

    qlstm_stage1<<<1, 256>>>(qw, Wo, bo, fcW);
    qlstm_stage2<<<128, 256>>>(x, fcb, out);

    (void)in_sizes; (void)n_in; (void)out_size;
}

// round 3
// speedup vs baseline: 1.6882x; 1.6882x over previous
#include <cuda_runtime.h>
#include <cuda_bf16.h>

// s_t table: g_s[t] = (h_t . fcW[0,:], h_t . fcW[1,:]),  t in [0,128)
__device__ float2 g_s[128];
// Monotonic ticket counter for the grid barrier. Never reset: launch k uses
// tickets [128k, 128(k+1)), so it's deterministic across graph replays.
__device__ unsigned g_tickets;

__device__ __forceinline__ float sigmoidf_(float x) { return 1.0f / (1.0f + __expf(-x)); }

__global__ void __launch_bounds__(256, 1)
qlstm_fused(const int*   __restrict__ x,    // (1024,128)
            const float* __restrict__ qw,   // (4,2,8)
            const float* __restrict__ Wo,   // (4,256,8)
            const float* __restrict__ bo,   // (4,256)
            const float* __restrict__ fcW,  // (2,256)
            const float* __restrict__ fcb,  // (2,)
            float*       __restrict__ out)  // (1024,2)
{
    const int tid  = threadIdx.x;
    const int b    = blockIdx.x;          // 128 blocks: block b owns time-step t=b
    const int lane = tid & 31;
    const int wrp  = tid >> 5;            // 8 warps: warp w owns batch row b*8+w

    // ---- Prefetch this block's slice of x EARLY (hides cold-DRAM latency
    //      behind the stage-1 compute below). Row r = b*8+wrp, t = lane*4..+3.
    const int row = b * 8 + wrp;
    const int4 px = *(const int4*)(x + row * 128 + lane * 4);

    __shared__ float zeta_s[32];
    __shared__ float zz[32];              // zz[g*8+w] = Heisenberg Z-product
    __shared__ float red0[8], red1[8];
    __shared__ float2 s_s[128];

    // ---- Per-wire <Z> factor (RX embedding + RZ are provably unobservable):
    //      zeta[g][j] = -sin(qw[g,0,j])
    if (tid < 32) {
        int g = tid >> 3, j = tid & 7;
        zeta_s[tid] = -sinf(qw[g * 16 + j]);
    }
    __syncwarp();
    // CNOT-ring products: z[g][0] = prod_{j=1..7}, z[g][w>=1] = prod_{j=0..w}
    if (tid < 32) {
        int g = tid >> 3, w = tid & 7;
        float p = 1.0f;
        if (w == 0) { for (int j = 1; j < 8; j++)  p *= zeta_s[g * 8 + j]; }
        else        { for (int j = 0; j <= w; j++) p *= zeta_s[g * 8 + j]; }
        zz[tid] = p;
    }
    __syncthreads();

    // ---- Stage 1: constant gate pre-activations for hidden unit h = tid,
    //      closed-form c_t = ig * (1 - f^n)/(1 - f), n = b+1 (stable via expm1).
    const int h = tid;
    float pre[4];
#pragma unroll
    for (int g = 0; g < 4; g++) {
        const float4* wp = (const float4*)(Wo + (g * 256 + h) * 8);
        float4 wa = wp[0], wb = wp[1];
        const float* z = &zz[g * 8];
        pre[g] = bo[g * 256 + h]
               + wa.x * z[0] + wa.y * z[1] + wa.z * z[2] + wa.w * z[3]
               + wb.x * z[4] + wb.y * z[5] + wb.z * z[6] + wb.w * z[7];
    }
    const float lf = -log1pf(__expf(-pre[0]));                  // ln f, f=sigmoid(pre0)
    const float ig = sigmoidf_(pre[1]) * tanhf(pre[2]);
    const float oo = sigmoidf_(pre[3]);
    const float n  = (float)(b + 1);
    const float c  = ig * (expm1f(n * lf) / expm1f(lf));        // c_n
    const float hv = oo * tanhf(c);

    // Reduce over h: s0 = sum_h hv*fcW[0,h], s1 = sum_h hv*fcW[1,h]
    float s0 = hv * fcW[h];
    float s1 = hv * fcW[256 + h];
#pragma unroll
    for (int off = 16; off; off >>= 1) {
        s0 += __shfl_xor_sync(0xffffffffu, s0, off);
        s1 += __shfl_xor_sync(0xffffffffu, s1, off);
    }
    if (lane == 0) { red0[wrp] = s0; red1[wrp] = s1; }
    __syncthreads();
    if (tid == 0) {
        float t0 = 0.0f, t1 = 0.0f;
#pragma unroll
        for (int k = 0; k < 8; k++) { t0 += red0[k]; t1 += red1[k]; }
        g_s[b] = make_float2(t0, t1);
        __threadfence();
        // ---- Grid barrier (ticket-based, replay-safe)
        unsigned old    = atomicAdd(&g_tickets, 1u);
        unsigned target = ((old >> 7) + 1u) << 7;     // end of this launch's cohort
        while ((int)(atomicAdd(&g_tickets, 0u) - target) < 0) { }
        __threadfence();
    }
    __syncthreads();

    // ---- Stage 2: combine prefetched mask bits with the now-complete s table.
    if (tid < 128) s_s[tid] = __ldcg(&g_s[tid]);      // L2-fresh (bypass L1)
    __syncthreads();

    const int tb = lane * 4;
    float a0 = 0.0f, a1 = 0.0f, cnt = 0.0f;
    float m;
    m = (px.x != 0) ? 1.0f : 0.0f; a0 += m * s_s[tb + 0].x; a1 += m * s_s[tb + 0].y; cnt += m;
    m = (px.y != 0) ? 1.0f : 0.0f; a0 += m * s_s[tb + 1].x; a1 += m * s_s[tb + 1].y; cnt += m;
    m = (px.z != 0) ? 1.0f : 0.0f; a0 += m * s_s[tb + 2].x; a1 += m * s_s[tb + 2].y; cnt += m;
    m = (px.w != 0) ? 1.0f : 0.0f; a0 += m * s_s[tb + 3].x; a1 += m * s_s[tb + 3].y; cnt += m;
#pragma unroll
    for (int off = 16; off; off >>= 1) {
        a0  += __shfl_xor_sync(0xffffffffu, a0, off);
        a1  += __shfl_xor_sync(0xffffffffu, a1, off);
        cnt += __shfl_xor_sync(0xffffffffu, cnt, off);
    }
    if (lane == 0) {
        float inv = 1.0f / (cnt + 1e-9f);
        out[row * 2 + 0] = a0 * inv + fcb[0];
        out[row * 2 + 1] = a1 * inv + fcb[1];
    }
}

extern "C" void kernel_launch(void* const* d_in, const int* in_sizes, int n_in,
                              void* d_out, int out_size)
{
    // metadata order: x, embed, Wi, bi, qw, Wo, bo, fcW, fcb
    const int*   x   = (const int*)  d_in[0];
    const float* qw  = (const float*)d_in[4];
    const float* Wo  = (const float*)d_in[5];
    const float* bo  = (const float*)d_in[6];
    const float* fcW = (const float*)d_in[7];
    const float* fcb = (const float*)d_in[8];
    float* out = (float*)d_out;

    qlstm_fused<<<128, 256>>>(x, qw, Wo, bo, fcW, fcb, out);

    (void)in_sizes; (void)n_in; (void)out_size;
}